// round 1
// baseline (speedup 1.0000x reference)
#include <cuda_runtime.h>
#include <math.h>

#define T 512
#define B 128
#define H 512
#define NF 128
#define FS 5
#define M_TOTAL 1920  /* NF * (1+2+3+4+5) */

// Scratch (static __device__ arrays: allocation-guard safe)
__device__ float g_X[(size_t)B * H * T];          // 134 MB, (B,H,T) t-contiguous
__device__ float g_W[(size_t)M_TOTAL * H];        // 3.9 MB, row j = (w,dw,f), k-contiguous
__device__ float g_C[(size_t)B * M_TOTAL * T];    // 503 MB conv outputs

// ---------------------------------------------------------------------------
// Pack weights: g_W[j][h] = conv_w{w}[f,0,h,dw], j = off_w + dw*NF + f
// ---------------------------------------------------------------------------
__global__ void pack_w_kernel(const float* __restrict__ w1, const float* __restrict__ w2,
                              const float* __restrict__ w3, const float* __restrict__ w4,
                              const float* __restrict__ w5) {
    int idx = blockIdx.x * blockDim.x + threadIdx.x;
    if (idx >= M_TOTAL * H) return;
    int h = idx & (H - 1);
    int j = idx >> 9;
    int w, off;
    if (j < 128)       { w = 1; off = 0;    }
    else if (j < 384)  { w = 2; off = 128;  }
    else if (j < 768)  { w = 3; off = 384;  }
    else if (j < 1280) { w = 4; off = 768;  }
    else               { w = 5; off = 1280; }
    int r  = j - off;
    int dw = r >> 7;    // / NF
    int f  = r & 127;   // % NF
    const float* wp = (w == 1) ? w1 : (w == 2) ? w2 : (w == 3) ? w3 : (w == 4) ? w4 : w5;
    g_W[idx] = wp[(size_t)f * H * w + (size_t)h * w + dw];
}

// ---------------------------------------------------------------------------
// Pack X: g_X[b][h][t] = flat_b[h*L + t] (t < L) else 0,
// where flat_b is encoder_output[:, b, :] flattened over (T, H).
// ---------------------------------------------------------------------------
__global__ void pack_x_kernel(const float* __restrict__ enc, const int* __restrict__ lengths) {
    int idx = blockIdx.x * blockDim.x + threadIdx.x;  // over B*H*T
    int t = idx & (T - 1);
    int h = (idx >> 9) & (H - 1);
    int b = idx >> 18;
    int L = lengths[b];
    float v = 0.0f;
    if (t < L) {
        int i = h * L + t;                       // < H*T, fits int
        v = enc[(size_t)(i >> 9) * (B * H) + (size_t)b * H + (i & (H - 1))];
    }
    g_X[idx] = v;
}

// ---------------------------------------------------------------------------
// Batched GEMM: C[b][j][t] = sum_h g_W[j][h] * g_X[b][h][t]
// Tile 64(M) x 64(N) x 16(K), 256 threads, 4x4 micro-tile/thread.
// Skips t-tiles beyond Leff_b (only those are ever read by the pool kernel).
// ---------------------------------------------------------------------------
__global__ void __launch_bounds__(256) gemm_kernel(const int* __restrict__ lengths) {
    int b = blockIdx.z;
    int L = lengths[b];
    int Leff = (L > FS) ? L : FS;
    int t0 = blockIdx.x * 64;
    if (t0 >= Leff) return;
    int j0 = blockIdx.y * 64;

    __shared__ float As[16][64];  // As[k][j]
    __shared__ float Bs[16][64];  // Bs[k][t]

    int tid = threadIdx.x;
    int ty = tid >> 4;        // 0..15 (j groups of 4)
    int tx = tid & 15;        // 0..15 (t groups of 4)

    float acc[4][4] = {};

    const float* Wb = g_W + (size_t)j0 * H;
    const float* Xb = g_X + (size_t)b * H * T + t0;

    int aj = tid >> 2;        // 0..63
    int ak = (tid & 3) * 4;   // 0,4,8,12
    int bk = tid >> 4;        // 0..15
    int bt = (tid & 15) * 4;  // 0..60

    for (int k0 = 0; k0 < H; k0 += 16) {
        float4 av = *(const float4*)&Wb[(size_t)aj * H + k0 + ak];
        As[ak + 0][aj] = av.x;
        As[ak + 1][aj] = av.y;
        As[ak + 2][aj] = av.z;
        As[ak + 3][aj] = av.w;
        float4 bv = *(const float4*)&Xb[(size_t)(k0 + bk) * T + bt];
        *(float4*)&Bs[bk][bt] = bv;
        __syncthreads();
        #pragma unroll
        for (int kk = 0; kk < 16; kk++) {
            float4 a  = *(const float4*)&As[kk][ty * 4];
            float4 bb = *(const float4*)&Bs[kk][tx * 4];
            float ar[4] = {a.x, a.y, a.z, a.w};
            float br[4] = {bb.x, bb.y, bb.z, bb.w};
            #pragma unroll
            for (int i = 0; i < 4; i++)
                #pragma unroll
                for (int jj = 0; jj < 4; jj++)
                    acc[i][jj] += ar[i] * br[jj];
        }
        __syncthreads();
    }

    float* Cb = g_C + ((size_t)b * M_TOTAL + j0 + ty * 4) * T + t0 + tx * 4;
    #pragma unroll
    for (int i = 0; i < 4; i++) {
        float4 o = make_float4(acc[i][0], acc[i][1], acc[i][2], acc[i][3]);
        *(float4*)(Cb + (size_t)i * T) = o;
    }
}

// ---------------------------------------------------------------------------
// Pool + FC1 + FC2 + sigmoid. One block per batch.
// pool(w,f) = max(0, max_{t<=Leff-w} [ bias_w[f] + sum_dw C[b, off_w+dw*NF+f, t+dw] ])
// ---------------------------------------------------------------------------
__global__ void __launch_bounds__(256) pool_fc_kernel(
    const int* __restrict__ lengths,
    const float* __restrict__ b1, const float* __restrict__ b2,
    const float* __restrict__ b3, const float* __restrict__ b4,
    const float* __restrict__ b5,
    const float* __restrict__ fc1_w, const float* __restrict__ fc1_b,
    const float* __restrict__ fc2_w, const float* __restrict__ fc2_b,
    float* __restrict__ out)
{
    int b = blockIdx.x;
    int L = lengths[b];
    int Leff = (L > FS) ? L : FS;

    __shared__ float feat[5 * NF];
    __shared__ float fc1[100];

    int tid  = threadIdx.x;
    int warp = tid >> 5;
    int lane = tid & 31;

    const float* biases[5] = {b1, b2, b3, b4, b5};
    const int offs[5] = {0, 128, 384, 768, 1280};

    for (int p = warp; p < 5 * NF; p += 8) {
        int w = p / NF + 1;
        int f = p % NF;
        float bias = biases[w - 1][f];
        const float* Cb = g_C + ((size_t)b * M_TOTAL + offs[w - 1] + f) * T;
        float m = 0.0f;                    // relu/mask floor
        int tmax = Leff - w;               // inclusive
        for (int t = lane; t <= tmax; t += 32) {
            float s = bias;
            #pragma unroll
            for (int dw = 0; dw < FS; dw++) {
                if (dw < w) s += Cb[(size_t)dw * NF * T + t + dw];
            }
            m = fmaxf(m, s);
        }
        #pragma unroll
        for (int o = 16; o > 0; o >>= 1)
            m = fmaxf(m, __shfl_xor_sync(0xffffffffu, m, o));
        if (lane == 0) feat[p] = m;
    }
    __syncthreads();

    if (tid < 100) {
        float s = fc1_b[tid];
        const float* wrow = fc1_w + (size_t)tid * (5 * NF);
        #pragma unroll 8
        for (int j = 0; j < 5 * NF; j++) s += feat[j] * wrow[j];
        fc1[tid] = s;
    }
    __syncthreads();

    if (tid == 0) {
        float s = fc2_b[0];
        for (int o = 0; o < 100; o++) s += fc1[o] * fc2_w[o];
        out[b] = 1.0f / (1.0f + expf(-s));
    }
}

// ---------------------------------------------------------------------------
extern "C" void kernel_launch(void* const* d_in, const int* in_sizes, int n_in,
                              void* d_out, int out_size) {
    const float* enc     = (const float*)d_in[0];
    const int*   lengths = (const int*)d_in[1];
    const float* w1 = (const float*)d_in[2];
    const float* cb1 = (const float*)d_in[3];
    const float* w2 = (const float*)d_in[4];
    const float* cb2 = (const float*)d_in[5];
    const float* w3 = (const float*)d_in[6];
    const float* cb3 = (const float*)d_in[7];
    const float* w4 = (const float*)d_in[8];
    const float* cb4 = (const float*)d_in[9];
    const float* w5 = (const float*)d_in[10];
    const float* cb5 = (const float*)d_in[11];
    const float* fc1_w = (const float*)d_in[12];
    const float* fc1_b = (const float*)d_in[13];
    const float* fc2_w = (const float*)d_in[14];
    const float* fc2_b = (const float*)d_in[15];
    float* out = (float*)d_out;

    pack_w_kernel<<<(M_TOTAL * H + 255) / 256, 256>>>(w1, w2, w3, w4, w5);
    pack_x_kernel<<<(B * H * T) / 256, 256>>>(enc, lengths);
    gemm_kernel<<<dim3(T / 64, M_TOTAL / 64, B), 256>>>(lengths);
    pool_fc_kernel<<<B, 256>>>(lengths, cb1, cb2, cb3, cb4, cb5,
                               fc1_w, fc1_b, fc2_w, fc2_b, out);
}

// round 3
// speedup vs baseline: 3.2983x; 3.2983x over previous
#include <cuda_runtime.h>
#include <cuda_bf16.h>
#include <cstdint>
#include <math.h>

#define T 512
#define B 128
#define H 512
#define NF 128
#define FS 5
#define M_TOTAL 1920  /* NF * (1+2+3+4+5) */

// ---------------------------------------------------------------------------
// Scratch (__device__ globals: allocation-guard safe)
// ---------------------------------------------------------------------------
__device__ __nv_bfloat16 g_Wh[(size_t)M_TOTAL * H];   // weights hi  [j][h]
__device__ __nv_bfloat16 g_Wl[(size_t)M_TOTAL * H];   // weights lo  [j][h]
__device__ __nv_bfloat16 g_Xh[(size_t)B * T * H];     // X hi [b][t][h]
__device__ __nv_bfloat16 g_Xl[(size_t)B * T * H];     // X lo [b][t][h]
__device__ float g_C[(size_t)B * M_TOTAL * T];        // conv outputs [b][j][t]
__device__ float g_feat[(size_t)B * 5 * NF];          // pooled features

// ---------------------------------------------------------------------------
// Portable PTX helpers (all valid at compute_103 virtual arch)
// ---------------------------------------------------------------------------
__device__ __forceinline__ uint32_t smem_to_u32(const void* p) {
    uint32_t a;
    asm("{ .reg .u64 t; cvta.to.shared.u64 t, %1; cvt.u32.u64 %0, t; }" : "=r"(a) : "l"(p));
    return a;
}
#define SMEM_SWIZZLE_128B(off) ((off) ^ (((off) >> 3) & 0x70))

#define CP_ASYNC_16(dst, src) \
    asm volatile("cp.async.cg.shared.global [%0], [%1], 16;" :: "r"(dst), "l"(src))
#define CP_ASYNC_COMMIT() asm volatile("cp.async.commit_group;" ::: "memory")
#define CP_ASYNC_WAIT(n)  asm volatile("cp.async.wait_group %0;" :: "n"(n) : "memory")

__device__ __forceinline__ void ldsm_x4(uint32_t* r, uint32_t addr) {
    asm volatile("ldmatrix.sync.aligned.m8n8.x4.shared.b16 {%0,%1,%2,%3}, [%4];"
                 : "=r"(r[0]), "=r"(r[1]), "=r"(r[2]), "=r"(r[3]) : "r"(addr));
}

__device__ __forceinline__ void mma_bf16(float* c, const uint32_t* a, const uint32_t* b) {
    asm volatile(
        "mma.sync.aligned.m16n8k16.row.col.f32.bf16.bf16.f32 "
        "{%0,%1,%2,%3}, {%4,%5,%6,%7}, {%8,%9}, {%0,%1,%2,%3};"
        : "+f"(c[0]), "+f"(c[1]), "+f"(c[2]), "+f"(c[3])
        : "r"(a[0]), "r"(a[1]), "r"(a[2]), "r"(a[3]), "r"(b[0]), "r"(b[1]));
}

// ---------------------------------------------------------------------------
// Pack weights -> bf16 hi/lo, g_W*[j][h], j = off_w + dw*NF + f
// ---------------------------------------------------------------------------
__global__ void pack_w_kernel(const float* __restrict__ w1, const float* __restrict__ w2,
                              const float* __restrict__ w3, const float* __restrict__ w4,
                              const float* __restrict__ w5) {
    int idx = blockIdx.x * blockDim.x + threadIdx.x;
    if (idx >= M_TOTAL * H) return;
    int h = idx & (H - 1);
    int j = idx >> 9;
    int w, off;
    if (j < 128)       { w = 1; off = 0;    }
    else if (j < 384)  { w = 2; off = 128;  }
    else if (j < 768)  { w = 3; off = 384;  }
    else if (j < 1280) { w = 4; off = 768;  }
    else               { w = 5; off = 1280; }
    int r  = j - off;
    int dw = r >> 7;
    int f  = r & 127;
    const float* wp = (w == 1) ? w1 : (w == 2) ? w2 : (w == 3) ? w3 : (w == 4) ? w4 : w5;
    float v = wp[(size_t)f * H * w + (size_t)h * w + dw];
    __nv_bfloat16 hi = __float2bfloat16(v);
    float lo = v - __bfloat162float(hi);
    g_Wh[idx] = hi;
    g_Wl[idx] = __float2bfloat16(lo);
}

// ---------------------------------------------------------------------------
// Fused gather + transpose pack of X: g_X*[b][t][h] (h contiguous), bf16 hi/lo
// ---------------------------------------------------------------------------
__global__ void __launch_bounds__(256) pack_xt_kernel(const float* __restrict__ enc,
                                                      const int* __restrict__ lengths) {
    __shared__ float tile[32][33];
    int b  = blockIdx.z;
    int t0 = blockIdx.x * 32;
    int h0 = blockIdx.y * 32;
    int L  = lengths[b];
    int tid = threadIdx.x, wid = tid >> 5, lane = tid & 31;
    int t = t0 + lane;
    #pragma unroll
    for (int k = 0; k < 4; k++) {
        int hl = wid * 4 + k;
        float v = 0.0f;
        if (t < L) {
            int i = (h0 + hl) * L + t;
            v = enc[(size_t)(i >> 9) * (B * H) + (size_t)b * H + (i & (H - 1))];
        }
        tile[hl][lane] = v;
    }
    __syncthreads();
    #pragma unroll
    for (int k = 0; k < 4; k++) {
        int tl = wid * 4 + k;
        float v = tile[lane][tl];
        __nv_bfloat16 hi = __float2bfloat16(v);
        float lo = v - __bfloat162float(hi);
        size_t o = ((size_t)b * T + t0 + tl) * H + h0 + lane;
        g_Xh[o] = hi;
        g_Xl[o] = __float2bfloat16(lo);
    }
}

// ---------------------------------------------------------------------------
// HMMA GEMM: C[b][j][t] = sum_h W[j,h]*X[b,h,t], fp32 via bf16 hi/lo 3-pass.
// CTA tile 128x128, warp tile 64x32 (2x4 warps), K-chunk 64, 2-stage cp.async.
// smem stage: Ah|Al|Bh|Bl, each 128x64 bf16 (16KB, SW128), stage=64KB.
// ---------------------------------------------------------------------------
#define GEMM_SMEM_BYTES 131072

__global__ void __launch_bounds__(256, 1) gemm_kernel(const int* __restrict__ lengths) {
    extern __shared__ char smem[];
    int b = blockIdx.z;
    int L = lengths[b];
    int Leff = (L > FS) ? L : FS;
    int t0 = blockIdx.x * 128;
    if (t0 >= Leff) return;
    int j0 = blockIdx.y * 128;

    uint32_t sb = smem_to_u32(smem);
    int tid = threadIdx.x, wid = tid >> 5, lane = tid & 31;
    int wm = wid >> 2;        // 0..1 : m-offset wm*64
    int wn = wid & 3;         // 0..3 : n-offset wn*32

    const __nv_bfloat16* Wh = g_Wh + (size_t)j0 * H;
    const __nv_bfloat16* Wl = g_Wl + (size_t)j0 * H;
    const __nv_bfloat16* Xh = g_Xh + ((size_t)b * T + t0) * H;
    const __nv_bfloat16* Xl = g_Xl + ((size_t)b * T + t0) * H;

    // Per-thread load slots (16 cp.async per stage)
    auto load_stage = [&](int ch, int s) {
        uint32_t st = sb + (uint32_t)s * 65536u;
        #pragma unroll
        for (int q = 0; q < 4; q++) {
            int idx  = q * 256 + tid;        // 0..1023
            int row  = idx >> 3;             // 0..127
            int col8 = idx & 7;              // 16B column group
            uint32_t sw = SMEM_SWIZZLE_128B((uint32_t)(row * 128 + col8 * 16));
            size_t src = (size_t)row * H + ch * 64 + col8 * 8;
            CP_ASYNC_16(st + sw,          Wh + src);
            CP_ASYNC_16(st + 16384u + sw, Wl + src);
            CP_ASYNC_16(st + 32768u + sw, Xh + src);
            CP_ASYNC_16(st + 49152u + sw, Xl + src);
        }
        CP_ASYNC_COMMIT();
    };

    float acc[4][4][4];
    #pragma unroll
    for (int mi = 0; mi < 4; mi++)
        #pragma unroll
        for (int ni = 0; ni < 4; ni++)
            #pragma unroll
            for (int e = 0; e < 4; e++) acc[mi][ni][e] = 0.0f;

    load_stage(0, 0);

    #pragma unroll 1
    for (int ch = 0; ch < 8; ch++) {
        int s = ch & 1;
        if (ch < 7) { load_stage(ch + 1, s ^ 1); CP_ASYNC_WAIT(1); }
        else        { CP_ASYNC_WAIT(0); }
        __syncthreads();

        uint32_t st = sb + (uint32_t)s * 65536u;
        const uint32_t offA[3] = { 0u, 0u, 16384u };        // Ah, Ah, Al
        const uint32_t offB[3] = { 32768u, 49152u, 32768u };// Bh, Bl, Bh

        #pragma unroll
        for (int p = 0; p < 3; p++) {
            uint32_t Ab = st + offA[p];
            uint32_t Bb = st + offB[p];
            #pragma unroll
            for (int ks = 0; ks < 4; ks++) {
                int k0 = ks * 16;
                uint32_t a[4][4];
                #pragma unroll
                for (int mi = 0; mi < 4; mi++) {
                    int row = wm * 64 + mi * 16 + ((lane >> 3) & 1) * 8 + (lane & 7);
                    int col = k0 + (lane >> 4) * 8;
                    uint32_t off = (uint32_t)(row * 128 + col * 2);
                    ldsm_x4(a[mi], Ab + SMEM_SWIZZLE_128B(off));
                }
                uint32_t bb[2][4];
                #pragma unroll
                for (int nh = 0; nh < 2; nh++) {
                    int row = wn * 32 + nh * 16 + (lane >> 4) * 8 + (lane & 7);
                    int col = k0 + ((lane >> 3) & 1) * 8;
                    uint32_t off = (uint32_t)(row * 128 + col * 2);
                    ldsm_x4(bb[nh], Bb + SMEM_SWIZZLE_128B(off));
                }
                #pragma unroll
                for (int mi = 0; mi < 4; mi++)
                    #pragma unroll
                    for (int ni = 0; ni < 4; ni++)
                        mma_bf16(acc[mi][ni], a[mi], &bb[ni >> 1][(ni & 1) * 2]);
            }
        }
        __syncthreads();
    }

    // Epilogue: write fp32 C
    #pragma unroll
    for (int mi = 0; mi < 4; mi++) {
        #pragma unroll
        for (int ni = 0; ni < 4; ni++) {
            int j = j0 + wm * 64 + mi * 16 + (lane >> 2);
            int t = t0 + wn * 32 + ni * 8 + (lane & 3) * 2;
            float* base = g_C + ((size_t)b * M_TOTAL + j) * T + t;
            *(float2*)base             = make_float2(acc[mi][ni][0], acc[mi][ni][1]);
            *(float2*)(base + 8 * T)   = make_float2(acc[mi][ni][2], acc[mi][ni][3]);
        }
    }
}

// ---------------------------------------------------------------------------
// Pool: feat[b][p] = max(0, max_t [bias + sum_dw C[b, off_w+dw*NF+f, t+dw]])
// ---------------------------------------------------------------------------
__global__ void __launch_bounds__(256) pool_kernel(
    const int* __restrict__ lengths,
    const float* __restrict__ b1, const float* __restrict__ b2,
    const float* __restrict__ b3, const float* __restrict__ b4,
    const float* __restrict__ b5)
{
    int b = blockIdx.x;
    int L = lengths[b];
    int Leff = (L > FS) ? L : FS;
    int tid = threadIdx.x, warp = tid >> 5, lane = tid & 31;

    const float* biases[5] = { b1, b2, b3, b4, b5 };
    const int offs[5] = { 0, 128, 384, 768, 1280 };

    int p_base = (blockIdx.y * 8 + warp) * 4;
    #pragma unroll
    for (int i = 0; i < 4; i++) {
        int p = p_base + i;
        int w = (p >> 7) + 1;
        int f = p & 127;
        float bias = biases[w - 1][f];
        const float* Cb = g_C + ((size_t)b * M_TOTAL + offs[w - 1] + f) * T;
        float m = 0.0f;
        int tmax = Leff - w;
        for (int t = lane; t <= tmax; t += 32) {
            float s = bias;
            #pragma unroll
            for (int dw = 0; dw < FS; dw++) {
                if (dw < w) s += Cb[(size_t)dw * NF * T + t + dw];
            }
            m = fmaxf(m, s);
        }
        #pragma unroll
        for (int o = 16; o > 0; o >>= 1)
            m = fmaxf(m, __shfl_xor_sync(0xffffffffu, m, o));
        if (lane == 0) g_feat[(size_t)b * (5 * NF) + p] = m;
    }
}

// ---------------------------------------------------------------------------
// FC1 + FC2 + sigmoid
// ---------------------------------------------------------------------------
__global__ void __launch_bounds__(128) fc_kernel(
    const float* __restrict__ fc1_w, const float* __restrict__ fc1_b,
    const float* __restrict__ fc2_w, const float* __restrict__ fc2_b,
    float* __restrict__ out)
{
    int b = blockIdx.x;
    int tid = threadIdx.x;
    __shared__ float feat[5 * NF];
    __shared__ float fc1s[100];
    for (int i = tid; i < 5 * NF; i += 128) feat[i] = g_feat[(size_t)b * (5 * NF) + i];
    __syncthreads();
    if (tid < 100) {
        float s = fc1_b[tid];
        const float* wrow = fc1_w + (size_t)tid * (5 * NF);
        #pragma unroll 8
        for (int j = 0; j < 5 * NF; j++) s += feat[j] * wrow[j];
        fc1s[tid] = s;
    }
    __syncthreads();
    if (tid == 0) {
        float s = fc2_b[0];
        for (int o = 0; o < 100; o++) s += fc1s[o] * fc2_w[o];
        out[b] = 1.0f / (1.0f + expf(-s));
    }
}

// ---------------------------------------------------------------------------
extern "C" void kernel_launch(void* const* d_in, const int* in_sizes, int n_in,
                              void* d_out, int out_size) {
    const float* enc     = (const float*)d_in[0];
    const int*   lengths = (const int*)d_in[1];
    const float* w1 = (const float*)d_in[2];
    const float* cb1 = (const float*)d_in[3];
    const float* w2 = (const float*)d_in[4];
    const float* cb2 = (const float*)d_in[5];
    const float* w3 = (const float*)d_in[6];
    const float* cb3 = (const float*)d_in[7];
    const float* w4 = (const float*)d_in[8];
    const float* cb4 = (const float*)d_in[9];
    const float* w5 = (const float*)d_in[10];
    const float* cb5 = (const float*)d_in[11];
    const float* fc1_w = (const float*)d_in[12];
    const float* fc1_b = (const float*)d_in[13];
    const float* fc2_w = (const float*)d_in[14];
    const float* fc2_b = (const float*)d_in[15];
    float* out = (float*)d_out;

    cudaFuncSetAttribute(gemm_kernel, cudaFuncAttributeMaxDynamicSharedMemorySize, GEMM_SMEM_BYTES);

    pack_w_kernel<<<(M_TOTAL * H + 255) / 256, 256>>>(w1, w2, w3, w4, w5);
    pack_xt_kernel<<<dim3(T / 32, H / 32, B), 256>>>(enc, lengths);
    gemm_kernel<<<dim3(T / 128, M_TOTAL / 128, B), 256, GEMM_SMEM_BYTES>>>(lengths);
    pool_kernel<<<dim3(B, 20), 256>>>(lengths, cb1, cb2, cb3, cb4, cb5);
    fc_kernel<<<B, 128>>>(fc1_w, fc1_b, fc2_w, fc2_b, out);
}

// round 5
// speedup vs baseline: 5.3057x; 1.6086x over previous
#include <cuda_runtime.h>
#include <cuda_fp16.h>
#include <cstdint>
#include <math.h>

#define T 512
#define TP 520            /* T + 8 zero-pad rows for dw-shifted B reads */
#define B 128
#define H 512
#define NF 128
#define FS 5
#define W_ELEMS 983040    /* 128 * 512 * 15 */

// ---------------------------------------------------------------------------
// Scratch (__device__ globals: allocation-guard safe)
// ---------------------------------------------------------------------------
__device__ __align__(16) __half g_W[W_ELEMS];                 // [sec w][f][k=dw*512+h]
__device__ __align__(16) __half g_Xh[(size_t)B * TP * H];     // X hi fp16 [b][t][h]
__device__ __align__(16) __half g_Xl[(size_t)B * TP * H];     // X lo fp16 [b][t][h]
__device__ float g_feat[(size_t)B * 5 * NF];                  // pooled features

// ---------------------------------------------------------------------------
// Portable PTX helpers (valid at compute_103 virtual arch)
// ---------------------------------------------------------------------------
__device__ __forceinline__ uint32_t smem_to_u32(const void* p) {
    uint32_t a;
    asm("{ .reg .u64 t; cvta.to.shared.u64 t, %1; cvt.u32.u64 %0, t; }" : "=r"(a) : "l"(p));
    return a;
}
#define SMEM_SWIZZLE_128B(off) ((off) ^ (((off) >> 3) & 0x70))

#define CP_ASYNC_16(dst, src) \
    asm volatile("cp.async.cg.shared.global [%0], [%1], 16;" :: "r"(dst), "l"(src))
#define CP_ASYNC_COMMIT() asm volatile("cp.async.commit_group;" ::: "memory")
#define CP_ASYNC_WAIT(n)  asm volatile("cp.async.wait_group %0;" :: "n"(n) : "memory")

__device__ __forceinline__ void ldsm_x4(uint32_t* r, uint32_t addr) {
    asm volatile("ldmatrix.sync.aligned.m8n8.x4.shared.b16 {%0,%1,%2,%3}, [%4];"
                 : "=r"(r[0]), "=r"(r[1]), "=r"(r[2]), "=r"(r[3]) : "r"(addr));
}

__device__ __forceinline__ void mma_f16(float* c, const uint32_t* a, const uint32_t* b) {
    asm volatile(
        "mma.sync.aligned.m16n8k16.row.col.f32.f16.f16.f32 "
        "{%0,%1,%2,%3}, {%4,%5,%6,%7}, {%8,%9}, {%0,%1,%2,%3};"
        : "+f"(c[0]), "+f"(c[1]), "+f"(c[2]), "+f"(c[3])
        : "r"(a[0]), "r"(a[1]), "r"(a[2]), "r"(a[3]), "r"(b[0]), "r"(b[1]));
}

// ---------------------------------------------------------------------------
// Pack weights -> fp16, g_W[soff(w) + f*(512w) + dw*512 + h].
// Also zeroes g_feat and the t >= T pad rows of g_Xh/g_Xl (replay-idempotent).
// ---------------------------------------------------------------------------
__global__ void pack_w_kernel(const float* __restrict__ w1, const float* __restrict__ w2,
                              const float* __restrict__ w3, const float* __restrict__ w4,
                              const float* __restrict__ w5) {
    int idx = blockIdx.x * blockDim.x + threadIdx.x;
    if (idx < B * 5 * NF) g_feat[idx] = 0.0f;
    if (idx < B * 8 * H) {                 // zero the 8 pad rows per batch
        int b = idx >> 12;                 // /(8*H)
        int r = idx & 4095;
        size_t o = (size_t)b * TP * H + (size_t)T * H + r;
        g_Xh[o] = __float2half(0.0f);
        g_Xl[o] = __float2half(0.0f);
    }
    if (idx >= W_ELEMS) return;
    int w, rel;
    if (idx < 65536)       { w = 1; rel = idx; }
    else if (idx < 196608) { w = 2; rel = idx - 65536; }
    else if (idx < 393216) { w = 3; rel = idx - 196608; }
    else if (idx < 655360) { w = 4; rel = idx - 393216; }
    else                   { w = 5; rel = idx - 655360; }
    int Kw = w << 9;
    int f  = rel / Kw;
    int k  = rel - f * Kw;
    int dw = k >> 9;
    int h  = k & 511;
    const float* wp = (w == 1) ? w1 : (w == 2) ? w2 : (w == 3) ? w3 : (w == 4) ? w4 : w5;
    g_W[idx] = __float2half(wp[(size_t)(f * H + h) * w + dw]);
}

// ---------------------------------------------------------------------------
// Fused gather + transpose pack of X: g_X{h,l}[b][t][h], fp16 hi/lo split.
// X[b,h,t] = flat_b[h*L+t] (t<L) else 0, flat_b = enc[:, b, :] flattened (T,H)
// ---------------------------------------------------------------------------
__global__ void __launch_bounds__(256) pack_xt_kernel(const float* __restrict__ enc,
                                                      const int* __restrict__ lengths) {
    __shared__ float tile[32][33];
    int b  = blockIdx.z;
    int t0 = blockIdx.x * 32;
    int h0 = blockIdx.y * 32;
    int L  = lengths[b];
    int tid = threadIdx.x, wid = tid >> 5, lane = tid & 31;
    int t = t0 + lane;
    #pragma unroll
    for (int k = 0; k < 4; k++) {
        int hl = wid * 4 + k;
        float v = 0.0f;
        if (t < L) {
            int i = (h0 + hl) * L + t;
            v = enc[(size_t)(i >> 9) * (B * H) + (size_t)b * H + (i & (H - 1))];
        }
        tile[hl][lane] = v;
    }
    __syncthreads();
    #pragma unroll
    for (int k = 0; k < 4; k++) {
        int tl = wid * 4 + k;
        float v = tile[lane][tl];
        __half hi = __float2half(v);
        float lo = v - __half2float(hi);
        size_t o = ((size_t)b * TP + t0 + tl) * H + h0 + lane;
        g_Xh[o] = hi;
        g_Xl[o] = __float2half(lo);
    }
}

// ---------------------------------------------------------------------------
// Fused conv-GEMM + bias + relu + masked max-pool.
// Section w: out(f,t) = sum_{dw<w, h} W[f,h,dw] * X[h, t+dw]  (K = 512*w)
// CTA tile 128(f) x 128(t), warp tile 64x32, K-chunk 64, 2-stage cp.async.
// 2-pass fp16: acc = W*Xh + W*Xl. Epilogue atomicMax into g_feat.
// smem stage: A(16KB) | Bh(16KB) | Bl(16KB) = 48KB; 2 stages = 96KB.
// ---------------------------------------------------------------------------
#define GEMM_SMEM_BYTES 98304

__global__ void __launch_bounds__(256) gemm_kernel(
    const int* __restrict__ lengths,
    const float* __restrict__ b1, const float* __restrict__ b2,
    const float* __restrict__ b3, const float* __restrict__ b4,
    const float* __restrict__ b5)
{
    extern __shared__ char smem[];
    int b = blockIdx.z;
    int w = blockIdx.y + 1;
    int L = lengths[b];
    int Leff = (L > FS) ? L : FS;
    int tmax = Leff - w;               // inclusive valid t
    int t0 = blockIdx.x * 128;
    if (t0 > tmax) return;

    const int soff_tab[5] = { 0, 65536, 196608, 393216, 655360 };
    const __half* Abase = g_W + soff_tab[w - 1];
    int Kw  = w << 9;
    int nch = w << 3;                  // K / 64

    uint32_t sb = smem_to_u32(smem);
    int tid = threadIdx.x, wid = tid >> 5, lane = tid & 31;
    int wm = wid >> 2;                 // 0..1 : rows wm*64
    int wn = wid & 3;                  // 0..3 : cols wn*32

    const __half* XhB = g_Xh + ((size_t)b * TP + t0) * H;
    const __half* XlB = g_Xl + ((size_t)b * TP + t0) * H;

    auto load_stage = [&](int c, int s) {
        uint32_t st = sb + (uint32_t)s * 49152u;
        int dw = c >> 3, cc = c & 7;
        #pragma unroll
        for (int q = 0; q < 4; q++) {
            int idx  = q * 256 + tid;  // 0..1023
            int row  = idx >> 3;       // 0..127
            int col8 = idx & 7;
            uint32_t sw = SMEM_SWIZZLE_128B((uint32_t)(row * 128 + col8 * 16));
            const __half* asrc = Abase + (size_t)row * Kw + c * 64 + col8 * 8;
            size_t bsrc = (size_t)(dw + row) * H + cc * 64 + col8 * 8;
            CP_ASYNC_16(st + sw,          asrc);
            CP_ASYNC_16(st + 16384u + sw, XhB + bsrc);
            CP_ASYNC_16(st + 32768u + sw, XlB + bsrc);
        }
        CP_ASYNC_COMMIT();
    };

    float acc[4][4][4];
    #pragma unroll
    for (int mi = 0; mi < 4; mi++)
        #pragma unroll
        for (int ni = 0; ni < 4; ni++)
            #pragma unroll
            for (int e = 0; e < 4; e++) acc[mi][ni][e] = 0.0f;

    load_stage(0, 0);

    #pragma unroll 1
    for (int c = 0; c < nch; c++) {
        int s = c & 1;
        if (c + 1 < nch) { load_stage(c + 1, s ^ 1); CP_ASYNC_WAIT(1); }
        else             { CP_ASYNC_WAIT(0); }
        __syncthreads();

        uint32_t st = sb + (uint32_t)s * 49152u;
        #pragma unroll
        for (int ks = 0; ks < 4; ks++) {
            int k0 = ks * 16;
            uint32_t a[4][4];
            #pragma unroll
            for (int mi = 0; mi < 4; mi++) {
                int row = wm * 64 + mi * 16 + ((lane >> 3) & 1) * 8 + (lane & 7);
                int col = k0 + (lane >> 4) * 8;
                ldsm_x4(a[mi], st + SMEM_SWIZZLE_128B((uint32_t)(row * 128 + col * 2)));
            }
            uint32_t bh[2][4], bl[2][4];
            #pragma unroll
            for (int nh = 0; nh < 2; nh++) {
                int row = wn * 32 + nh * 16 + (lane >> 4) * 8 + (lane & 7);
                int col = k0 + ((lane >> 3) & 1) * 8;
                uint32_t off = SMEM_SWIZZLE_128B((uint32_t)(row * 128 + col * 2));
                ldsm_x4(bh[nh], st + 16384u + off);
                ldsm_x4(bl[nh], st + 32768u + off);
            }
            #pragma unroll
            for (int mi = 0; mi < 4; mi++)
                #pragma unroll
                for (int ni = 0; ni < 4; ni++)
                    mma_f16(acc[mi][ni], a[mi], &bh[ni >> 1][(ni & 1) * 2]);
            #pragma unroll
            for (int mi = 0; mi < 4; mi++)
                #pragma unroll
                for (int ni = 0; ni < 4; ni++)
                    mma_f16(acc[mi][ni], a[mi], &bl[ni >> 1][(ni & 1) * 2]);
        }
        __syncthreads();
    }

    // Epilogue: masked max over t, + bias, relu floor, atomicMax into g_feat.
    const float* bias = (w == 1) ? b1 : (w == 2) ? b2 : (w == 3) ? b3 : (w == 4) ? b4 : b5;
    float* featb = g_feat + (size_t)b * (5 * NF) + (size_t)(w - 1) * NF;

    #pragma unroll
    for (int mi = 0; mi < 4; mi++) {
        int f0 = wm * 64 + mi * 16 + (lane >> 2);
        float m0 = -1e30f, m1 = -1e30f;
        #pragma unroll
        for (int ni = 0; ni < 4; ni++) {
            int t = t0 + wn * 32 + ni * 8 + (lane & 3) * 2;
            if (t <= tmax)     { m0 = fmaxf(m0, acc[mi][ni][0]); m1 = fmaxf(m1, acc[mi][ni][2]); }
            if (t + 1 <= tmax) { m0 = fmaxf(m0, acc[mi][ni][1]); m1 = fmaxf(m1, acc[mi][ni][3]); }
        }
        #pragma unroll
        for (int o = 1; o <= 2; o <<= 1) {
            m0 = fmaxf(m0, __shfl_xor_sync(0xffffffffu, m0, o));
            m1 = fmaxf(m1, __shfl_xor_sync(0xffffffffu, m1, o));
        }
        if ((lane & 3) == 0) {
            float fa = fmaxf(0.0f, m0 + bias[f0]);
            float fb = fmaxf(0.0f, m1 + bias[f0 + 8]);
            atomicMax((int*)&featb[f0],     __float_as_int(fa));
            atomicMax((int*)&featb[f0 + 8], __float_as_int(fb));
        }
    }
}

// ---------------------------------------------------------------------------
// FC1 + FC2 + sigmoid
// ---------------------------------------------------------------------------
__global__ void __launch_bounds__(128) fc_kernel(
    const float* __restrict__ fc1_w, const float* __restrict__ fc1_b,
    const float* __restrict__ fc2_w, const float* __restrict__ fc2_b,
    float* __restrict__ out)
{
    int b = blockIdx.x;
    int tid = threadIdx.x;
    __shared__ float feat[5 * NF];
    __shared__ float fc1s[100];
    for (int i = tid; i < 5 * NF; i += 128) feat[i] = g_feat[(size_t)b * (5 * NF) + i];
    __syncthreads();
    if (tid < 100) {
        float s = fc1_b[tid];
        const float* wrow = fc1_w + (size_t)tid * (5 * NF);
        #pragma unroll 8
        for (int j = 0; j < 5 * NF; j++) s += feat[j] * wrow[j];
        fc1s[tid] = s;
    }
    __syncthreads();
    if (tid == 0) {
        float s = fc2_b[0];
        for (int o = 0; o < 100; o++) s += fc1s[o] * fc2_w[o];
        out[b] = 1.0f / (1.0f + expf(-s));
    }
}

// ---------------------------------------------------------------------------
extern "C" void kernel_launch(void* const* d_in, const int* in_sizes, int n_in,
                              void* d_out, int out_size) {
    const float* enc     = (const float*)d_in[0];
    const int*   lengths = (const int*)d_in[1];
    const float* w1 = (const float*)d_in[2];
    const float* cb1 = (const float*)d_in[3];
    const float* w2 = (const float*)d_in[4];
    const float* cb2 = (const float*)d_in[5];
    const float* w3 = (const float*)d_in[6];
    const float* cb3 = (const float*)d_in[7];
    const float* w4 = (const float*)d_in[8];
    const float* cb4 = (const float*)d_in[9];
    const float* w5 = (const float*)d_in[10];
    const float* cb5 = (const float*)d_in[11];
    const float* fc1_w = (const float*)d_in[12];
    const float* fc1_b = (const float*)d_in[13];
    const float* fc2_w = (const float*)d_in[14];
    const float* fc2_b = (const float*)d_in[15];
    float* out = (float*)d_out;

    static bool s_attr_done = false;
    if (!s_attr_done) {
        cudaFuncSetAttribute(gemm_kernel, cudaFuncAttributeMaxDynamicSharedMemorySize,
                             GEMM_SMEM_BYTES);
        s_attr_done = true;
    }

    pack_w_kernel<<<(W_ELEMS + 255) / 256, 256>>>(w1, w2, w3, w4, w5);
    pack_xt_kernel<<<dim3(T / 32, H / 32, B), 256>>>(enc, lengths);
    gemm_kernel<<<dim3(T / 128, 5, B), 256, GEMM_SMEM_BYTES>>>(lengths, cb1, cb2, cb3, cb4, cb5);
    fc_kernel<<<B, 128>>>(fc1_w, fc1_b, fc2_w, fc2_b, out);
}

// round 6
// speedup vs baseline: 9.2710x; 1.7474x over previous
#include <cuda_runtime.h>
#include <cuda_fp16.h>
#include <cstdint>
#include <math.h>

#define T 512
#define TP 520            /* T + 8 zero-pad rows for dw-shifted B reads */
#define B 128
#define H 512
#define NF 128
#define FS 5
#define W_ELEMS 983040    /* 128 * 512 * 15 */

// ---------------------------------------------------------------------------
// Scratch (__device__ globals: allocation-guard safe)
// ---------------------------------------------------------------------------
__device__ __align__(16) __half g_W[W_ELEMS];                 // [sec w][f][k=dw*512+h]
__device__ __align__(16) __half g_X[(size_t)B * TP * H];      // X fp16 [b][t][h]
__device__ float g_feat[(size_t)B * 5 * NF];                  // pooled features

// ---------------------------------------------------------------------------
// Portable PTX helpers (valid at compute_103 virtual arch)
// ---------------------------------------------------------------------------
__device__ __forceinline__ uint32_t smem_to_u32(const void* p) {
    uint32_t a;
    asm("{ .reg .u64 t; cvta.to.shared.u64 t, %1; cvt.u32.u64 %0, t; }" : "=r"(a) : "l"(p));
    return a;
}
#define SMEM_SWIZZLE_128B(off) ((off) ^ (((off) >> 3) & 0x70))

#define CP_ASYNC_16(dst, src) \
    asm volatile("cp.async.cg.shared.global [%0], [%1], 16;" :: "r"(dst), "l"(src))
#define CP_ASYNC_COMMIT() asm volatile("cp.async.commit_group;" ::: "memory")
#define CP_ASYNC_WAIT(n)  asm volatile("cp.async.wait_group %0;" :: "n"(n) : "memory")

__device__ __forceinline__ void ldsm_x4(uint32_t* r, uint32_t addr) {
    asm volatile("ldmatrix.sync.aligned.m8n8.x4.shared.b16 {%0,%1,%2,%3}, [%4];"
                 : "=r"(r[0]), "=r"(r[1]), "=r"(r[2]), "=r"(r[3]) : "r"(addr));
}

__device__ __forceinline__ void mma_f16(float* c, const uint32_t* a, const uint32_t* b) {
    asm volatile(
        "mma.sync.aligned.m16n8k16.row.col.f32.f16.f16.f32 "
        "{%0,%1,%2,%3}, {%4,%5,%6,%7}, {%8,%9}, {%0,%1,%2,%3};"
        : "+f"(c[0]), "+f"(c[1]), "+f"(c[2]), "+f"(c[3])
        : "r"(a[0]), "r"(a[1]), "r"(a[2]), "r"(a[3]), "r"(b[0]), "r"(b[1]));
}

// ---------------------------------------------------------------------------
// Pack weights -> fp16, g_W[soff(w) + f*(512w) + dw*512 + h].
// Also zeroes g_feat and the t >= T pad rows of g_X (replay-idempotent).
// ---------------------------------------------------------------------------
__global__ void pack_w_kernel(const float* __restrict__ w1, const float* __restrict__ w2,
                              const float* __restrict__ w3, const float* __restrict__ w4,
                              const float* __restrict__ w5) {
    int idx = blockIdx.x * blockDim.x + threadIdx.x;
    if (idx < B * 5 * NF) g_feat[idx] = 0.0f;
    if (idx < B * 8 * H) {                 // zero the 8 pad rows per batch
        int b = idx >> 12;                 // /(8*H)
        int r = idx & 4095;
        g_X[(size_t)b * TP * H + (size_t)T * H + r] = __float2half(0.0f);
    }
    if (idx >= W_ELEMS) return;
    int w, rel;
    if (idx < 65536)       { w = 1; rel = idx; }
    else if (idx < 196608) { w = 2; rel = idx - 65536; }
    else if (idx < 393216) { w = 3; rel = idx - 196608; }
    else if (idx < 655360) { w = 4; rel = idx - 393216; }
    else                   { w = 5; rel = idx - 655360; }
    int Kw = w << 9;
    int f  = rel / Kw;
    int k  = rel - f * Kw;
    int dw = k >> 9;
    int h  = k & 511;
    const float* wp = (w == 1) ? w1 : (w == 2) ? w2 : (w == 3) ? w3 : (w == 4) ? w4 : w5;
    g_W[idx] = __float2half(wp[(size_t)(f * H + h) * w + dw]);
}

// ---------------------------------------------------------------------------
// Fused gather + transpose pack of X: g_X[b][t][h] fp16.
// X[b,h,t] = flat_b[h*L+t] (t<L) else 0, flat_b = enc[:, b, :] flattened (T,H)
// Tiles with t0 >= Leff are skipped: those rows only feed epilogue-masked
// columns of the GEMM (no cross-t mixing), so stale data there is harmless.
// ---------------------------------------------------------------------------
__global__ void __launch_bounds__(256) pack_xt_kernel(const float* __restrict__ enc,
                                                      const int* __restrict__ lengths) {
    __shared__ float tile[32][33];
    int b  = blockIdx.z;
    int L  = lengths[b];
    int Leff = (L > FS) ? L : FS;
    int t0 = blockIdx.x * 32;
    if (t0 >= Leff) return;
    int h0 = blockIdx.y * 32;
    int tid = threadIdx.x, wid = tid >> 5, lane = tid & 31;
    int t = t0 + lane;
    #pragma unroll
    for (int k = 0; k < 4; k++) {
        int hl = wid * 4 + k;
        float v = 0.0f;
        if (t < L) {
            int i = (h0 + hl) * L + t;
            v = enc[(size_t)(i >> 9) * (B * H) + (size_t)b * H + (i & (H - 1))];
        }
        tile[hl][lane] = v;
    }
    __syncthreads();
    #pragma unroll
    for (int k = 0; k < 4; k++) {
        int tl = wid * 4 + k;
        g_X[((size_t)b * TP + t0 + tl) * H + h0 + lane] = __float2half(tile[lane][tl]);
    }
}

// ---------------------------------------------------------------------------
// Fused conv-GEMM + bias + relu + masked max-pool (single-pass fp16).
// Section w: out(f,t) = sum_{dw<w, h} W[f,h,dw] * X[h, t+dw]  (K = 512*w)
// CTA tile 128(f) x 128(t), warp tile 64x32, K-chunk 64, 3-stage cp.async.
// smem stage: A(16KB) | B(16KB) = 32KB; 3 stages = 96KB -> 2 CTAs/SM.
// ---------------------------------------------------------------------------
#define GEMM_SMEM_BYTES 98304

__global__ void __launch_bounds__(256) gemm_kernel(
    const int* __restrict__ lengths,
    const float* __restrict__ b1, const float* __restrict__ b2,
    const float* __restrict__ b3, const float* __restrict__ b4,
    const float* __restrict__ b5)
{
    extern __shared__ char smem[];
    int b = blockIdx.z;
    int w = blockIdx.y + 1;
    int L = lengths[b];
    int Leff = (L > FS) ? L : FS;
    int tmax = Leff - w;               // inclusive valid t
    int t0 = blockIdx.x * 128;
    if (t0 > tmax) return;

    const int soff_tab[5] = { 0, 65536, 196608, 393216, 655360 };
    const __half* Abase = g_W + soff_tab[w - 1];
    int Kw  = w << 9;
    int nch = w << 3;                  // K / 64

    uint32_t sb = smem_to_u32(smem);
    int tid = threadIdx.x, wid = tid >> 5, lane = tid & 31;
    int wm = wid >> 2;                 // 0..1 : rows wm*64
    int wn = wid & 3;                  // 0..3 : cols wn*32

    const __half* XB = g_X + ((size_t)b * TP + t0) * H;

    auto load_stage = [&](int c, int s) {
        uint32_t st = sb + (uint32_t)s * 32768u;
        int dw = c >> 3, cc = c & 7;
        #pragma unroll
        for (int q = 0; q < 4; q++) {
            int idx  = q * 256 + tid;  // 0..1023
            int row  = idx >> 3;       // 0..127
            int col8 = idx & 7;
            uint32_t sw = SMEM_SWIZZLE_128B((uint32_t)(row * 128 + col8 * 16));
            CP_ASYNC_16(st + sw,          Abase + (size_t)row * Kw + c * 64 + col8 * 8);
            CP_ASYNC_16(st + 16384u + sw, XB + (size_t)(dw + row) * H + cc * 64 + col8 * 8);
        }
        CP_ASYNC_COMMIT();
    };

    float acc[4][4][4];
    #pragma unroll
    for (int mi = 0; mi < 4; mi++)
        #pragma unroll
        for (int ni = 0; ni < 4; ni++)
            #pragma unroll
            for (int e = 0; e < 4; e++) acc[mi][ni][e] = 0.0f;

    load_stage(0, 0);
    load_stage(1, 1);

    #pragma unroll 1
    for (int c = 0; c < nch; c++) {
        if (c + 2 < nch) { load_stage(c + 2, (c + 2) % 3); CP_ASYNC_WAIT(2); }
        else             { CP_ASYNC_WAIT(0); }
        __syncthreads();

        uint32_t st = sb + (uint32_t)(c % 3) * 32768u;
        #pragma unroll
        for (int ks = 0; ks < 4; ks++) {
            int k0 = ks * 16;
            uint32_t a[4][4];
            #pragma unroll
            for (int mi = 0; mi < 4; mi++) {
                int row = wm * 64 + mi * 16 + ((lane >> 3) & 1) * 8 + (lane & 7);
                int col = k0 + (lane >> 4) * 8;
                ldsm_x4(a[mi], st + SMEM_SWIZZLE_128B((uint32_t)(row * 128 + col * 2)));
            }
            uint32_t bh[2][4];
            #pragma unroll
            for (int nh = 0; nh < 2; nh++) {
                int row = wn * 32 + nh * 16 + (lane >> 4) * 8 + (lane & 7);
                int col = k0 + ((lane >> 3) & 1) * 8;
                ldsm_x4(bh[nh], st + 16384u + SMEM_SWIZZLE_128B((uint32_t)(row * 128 + col * 2)));
            }
            #pragma unroll
            for (int mi = 0; mi < 4; mi++)
                #pragma unroll
                for (int ni = 0; ni < 4; ni++)
                    mma_f16(acc[mi][ni], a[mi], &bh[ni >> 1][(ni & 1) * 2]);
        }
        __syncthreads();
    }

    // Epilogue: masked max over t, + bias, relu floor, atomicMax into g_feat.
    const float* bias = (w == 1) ? b1 : (w == 2) ? b2 : (w == 3) ? b3 : (w == 4) ? b4 : b5;
    float* featb = g_feat + (size_t)b * (5 * NF) + (size_t)(w - 1) * NF;

    #pragma unroll
    for (int mi = 0; mi < 4; mi++) {
        int f0 = wm * 64 + mi * 16 + (lane >> 2);
        float m0 = -1e30f, m1 = -1e30f;
        #pragma unroll
        for (int ni = 0; ni < 4; ni++) {
            int t = t0 + wn * 32 + ni * 8 + (lane & 3) * 2;
            if (t <= tmax)     { m0 = fmaxf(m0, acc[mi][ni][0]); m1 = fmaxf(m1, acc[mi][ni][2]); }
            if (t + 1 <= tmax) { m0 = fmaxf(m0, acc[mi][ni][1]); m1 = fmaxf(m1, acc[mi][ni][3]); }
        }
        #pragma unroll
        for (int o = 1; o <= 2; o <<= 1) {
            m0 = fmaxf(m0, __shfl_xor_sync(0xffffffffu, m0, o));
            m1 = fmaxf(m1, __shfl_xor_sync(0xffffffffu, m1, o));
        }
        if ((lane & 3) == 0) {
            float fa = fmaxf(0.0f, m0 + bias[f0]);
            float fb = fmaxf(0.0f, m1 + bias[f0 + 8]);
            atomicMax((int*)&featb[f0],     __float_as_int(fa));
            atomicMax((int*)&featb[f0 + 8], __float_as_int(fb));
        }
    }
}

// ---------------------------------------------------------------------------
// FC1 + FC2 + sigmoid, warp-parallel. One block per batch, 8 warps.
// ---------------------------------------------------------------------------
__global__ void __launch_bounds__(256) fc_kernel(
    const float* __restrict__ fc1_w, const float* __restrict__ fc1_b,
    const float* __restrict__ fc2_w, const float* __restrict__ fc2_b,
    float* __restrict__ out)
{
    int b = blockIdx.x;
    int tid = threadIdx.x, warp = tid >> 5, lane = tid & 31;
    __shared__ float feat[5 * NF];
    __shared__ float fc1s[100];

    for (int i = tid; i < 5 * NF; i += 256) feat[i] = g_feat[(size_t)b * (5 * NF) + i];
    __syncthreads();

    for (int o = warp; o < 100; o += 8) {
        const float* wrow = fc1_w + (size_t)o * (5 * NF);
        float s = 0.0f;
        #pragma unroll
        for (int k = 0; k < 20; k++) {
            int j = k * 32 + lane;
            s += feat[j] * wrow[j];
        }
        #pragma unroll
        for (int off = 16; off > 0; off >>= 1)
            s += __shfl_xor_sync(0xffffffffu, s, off);
        if (lane == 0) fc1s[o] = s + fc1_b[o];
    }
    __syncthreads();

    if (warp == 0) {
        float s = 0.0f;
        #pragma unroll
        for (int k = 0; k < 4; k++) {
            int o = k * 32 + lane;
            if (o < 100) s += fc1s[o] * fc2_w[o];
        }
        #pragma unroll
        for (int off = 16; off > 0; off >>= 1)
            s += __shfl_xor_sync(0xffffffffu, s, off);
        if (lane == 0) out[b] = 1.0f / (1.0f + expf(-(s + fc2_b[0])));
    }
}

// ---------------------------------------------------------------------------
extern "C" void kernel_launch(void* const* d_in, const int* in_sizes, int n_in,
                              void* d_out, int out_size) {
    const float* enc     = (const float*)d_in[0];
    const int*   lengths = (const int*)d_in[1];
    const float* w1 = (const float*)d_in[2];
    const float* cb1 = (const float*)d_in[3];
    const float* w2 = (const float*)d_in[4];
    const float* cb2 = (const float*)d_in[5];
    const float* w3 = (const float*)d_in[6];
    const float* cb3 = (const float*)d_in[7];
    const float* w4 = (const float*)d_in[8];
    const float* cb4 = (const float*)d_in[9];
    const float* w5 = (const float*)d_in[10];
    const float* cb5 = (const float*)d_in[11];
    const float* fc1_w = (const float*)d_in[12];
    const float* fc1_b = (const float*)d_in[13];
    const float* fc2_w = (const float*)d_in[14];
    const float* fc2_b = (const float*)d_in[15];
    float* out = (float*)d_out;

    static bool s_attr_done = false;
    if (!s_attr_done) {
        cudaFuncSetAttribute(gemm_kernel, cudaFuncAttributeMaxDynamicSharedMemorySize,
                             GEMM_SMEM_BYTES);
        s_attr_done = true;
    }

    pack_w_kernel<<<(W_ELEMS + 255) / 256, 256>>>(w1, w2, w3, w4, w5);
    pack_xt_kernel<<<dim3(T / 32, H / 32, B), 256>>>(enc, lengths);
    gemm_kernel<<<dim3(T / 128, 5, B), 256, GEMM_SMEM_BYTES>>>(lengths, cb1, cb2, cb3, cb4, cb5);
    fc_kernel<<<B, 256>>>(fc1_w, fc1_b, fc2_w, fc2_b, out);
}

// round 7
// speedup vs baseline: 10.8489x; 1.1702x over previous
#include <cuda_runtime.h>
#include <cuda_fp16.h>
#include <cstdint>
#include <math.h>

#define T 512
#define TP 520            /* T + 8 zero-pad rows for dw-shifted B reads */
#define B 128
#define H 512
#define NF 128
#define FS 5
#define W_ELEMS 983040    /* 128 * 512 * 15 */
#define PAD_ELEMS 524288  /* B * 8 * H */
#define FEAT_ELEMS 81920  /* B * 5 * NF */

// ---------------------------------------------------------------------------
// Scratch (__device__ globals: allocation-guard safe)
// ---------------------------------------------------------------------------
__device__ __align__(16) __half g_W[W_ELEMS];                 // [sec w][f][k=dw*512+h]
__device__ __align__(16) __half g_X[(size_t)B * TP * H];      // X fp16 [b][t][h]
__device__ float g_feat[(size_t)B * 5 * NF];                  // pooled features
__device__ float g_v[5 * NF];                                 // collapsed fc vector
__device__ float g_c[1];                                      // collapsed fc scalar

// ---------------------------------------------------------------------------
// Portable PTX helpers (valid at compute_103 virtual arch)
// ---------------------------------------------------------------------------
__device__ __forceinline__ uint32_t smem_to_u32(const void* p) {
    uint32_t a;
    asm("{ .reg .u64 t; cvta.to.shared.u64 t, %1; cvt.u32.u64 %0, t; }" : "=r"(a) : "l"(p));
    return a;
}
#define SMEM_SWIZZLE_128B(off) ((off) ^ (((off) >> 3) & 0x70))

#define CP_ASYNC_16(dst, src) \
    asm volatile("cp.async.cg.shared.global [%0], [%1], 16;" :: "r"(dst), "l"(src))
#define CP_ASYNC_COMMIT() asm volatile("cp.async.commit_group;" ::: "memory")
#define CP_ASYNC_WAIT(n)  asm volatile("cp.async.wait_group %0;" :: "n"(n) : "memory")

__device__ __forceinline__ void ldsm_x4(uint32_t* r, uint32_t addr) {
    asm volatile("ldmatrix.sync.aligned.m8n8.x4.shared.b16 {%0,%1,%2,%3}, [%4];"
                 : "=r"(r[0]), "=r"(r[1]), "=r"(r[2]), "=r"(r[3]) : "r"(addr));
}

__device__ __forceinline__ void mma_f16(float* c, const uint32_t* a, const uint32_t* b) {
    asm volatile(
        "mma.sync.aligned.m16n8k16.row.col.f32.f16.f16.f32 "
        "{%0,%1,%2,%3}, {%4,%5,%6,%7}, {%8,%9}, {%0,%1,%2,%3};"
        : "+f"(c[0]), "+f"(c[1]), "+f"(c[2]), "+f"(c[3])
        : "r"(a[0]), "r"(a[1]), "r"(a[2]), "r"(a[3]), "r"(b[0]), "r"(b[1]));
}

// ---------------------------------------------------------------------------
// Combined prep kernel. grid (16, 16, 153), block 256.
//  z <  128 : gather+transpose pack of X for batch z (pack_xt path)
//  z >= 128 : linearized aux work: W pack | pad-row zero | feat zero | fc collapse
// ---------------------------------------------------------------------------
__global__ void __launch_bounds__(256) prep_kernel(
    const float* __restrict__ enc, const int* __restrict__ lengths,
    const float* __restrict__ w1, const float* __restrict__ w2,
    const float* __restrict__ w3, const float* __restrict__ w4,
    const float* __restrict__ w5,
    const float* __restrict__ fc1_w, const float* __restrict__ fc1_b,
    const float* __restrict__ fc2_w, const float* __restrict__ fc2_b)
{
    int z = blockIdx.z;
    int tid = threadIdx.x;

    if (z < B) {
        // ---- pack_xt path ----
        __shared__ float tile[32][33];
        int b  = z;
        int L  = lengths[b];
        int Leff = (L > FS) ? L : FS;
        int t0 = blockIdx.x * 32;
        if (t0 >= Leff) return;     // masked-out tiles: stale data harmless
        int h0 = blockIdx.y * 32;
        int wid = tid >> 5, lane = tid & 31;
        int t = t0 + lane;
        #pragma unroll
        for (int k = 0; k < 4; k++) {
            int hl = wid * 4 + k;
            float v = 0.0f;
            if (t < L) {
                int i = (h0 + hl) * L + t;
                v = enc[(size_t)(i >> 9) * (B * H) + (size_t)b * H + (i & (H - 1))];
            }
            tile[hl][lane] = v;
        }
        __syncthreads();
        #pragma unroll
        for (int k = 0; k < 4; k++) {
            int tl = wid * 4 + k;
            g_X[((size_t)b * TP + t0 + tl) * H + h0 + lane] = __float2half(tile[lane][tl]);
        }
        return;
    }

    // ---- aux path ----
    int bi = (z - B) * 256 + blockIdx.y * 16 + blockIdx.x;   // 0..6399
    int g  = bi * 256 + tid;

    if (g < W_ELEMS) {
        int idx = g;
        int w, rel;
        if (idx < 65536)       { w = 1; rel = idx; }
        else if (idx < 196608) { w = 2; rel = idx - 65536; }
        else if (idx < 393216) { w = 3; rel = idx - 196608; }
        else if (idx < 655360) { w = 4; rel = idx - 393216; }
        else                   { w = 5; rel = idx - 655360; }
        int Kw = w << 9;
        int f  = rel / Kw;
        int k  = rel - f * Kw;
        int dw = k >> 9;
        int h  = k & 511;
        const float* wp = (w == 1) ? w1 : (w == 2) ? w2 : (w == 3) ? w3 : (w == 4) ? w4 : w5;
        g_W[idx] = __float2half(wp[(size_t)(f * H + h) * w + dw]);
        return;
    }
    int r = g - W_ELEMS;
    if (r < PAD_ELEMS) {            // zero the 8 pad rows per batch
        int b   = r >> 12;          // /(8*H)
        int off = r & 4095;
        g_X[(size_t)b * TP * H + (size_t)T * H + off] = __float2half(0.0f);
        return;
    }
    r -= PAD_ELEMS;
    if (r < FEAT_ELEMS) { g_feat[r] = 0.0f; return; }
    r -= FEAT_ELEMS;
    if (r < 5 * NF) {               // fc collapse: v[j] = sum_o fc2_w[o] * fc1_w[o][j]
        float s = 0.0f;
        #pragma unroll 4
        for (int o = 0; o < 100; o++) s += fc2_w[o] * fc1_w[(size_t)o * (5 * NF) + r];
        g_v[r] = s;
        if (r == 0) {
            float c = fc2_b[0];
            for (int o = 0; o < 100; o++) c += fc2_w[o] * fc1_b[o];
            g_c[0] = c;
        }
    }
}

// ---------------------------------------------------------------------------
// Fused conv-GEMM + bias + relu + masked max-pool (single-pass fp16).
// Section w: out(f,t) = sum_{dw<w, h} W[f,h,dw] * X[h, t+dw]  (K = 512*w)
// CTA tile 128(f) x 128(t), warp tile 64x32, K-chunk 64, 3-stage cp.async.
// LPT order: blockIdx.z slowest = w, with w=5 scheduled first.
// smem: 3 stages x 32KB = 96KB -> 2 CTAs/SM.
// ---------------------------------------------------------------------------
#define GEMM_SMEM_BYTES 98304

__global__ void __launch_bounds__(256) gemm_kernel(
    const int* __restrict__ lengths,
    const float* __restrict__ b1, const float* __restrict__ b2,
    const float* __restrict__ b3, const float* __restrict__ b4,
    const float* __restrict__ b5)
{
    extern __shared__ char smem[];
    int b = blockIdx.y;
    int w = 5 - blockIdx.z;            // LPT: longest CTAs (w=5) launch first
    int L = lengths[b];
    int Leff = (L > FS) ? L : FS;
    int tmax = Leff - w;               // inclusive valid t
    int t0 = blockIdx.x * 128;
    if (t0 > tmax) return;

    const int soff_tab[5] = { 0, 65536, 196608, 393216, 655360 };
    const __half* Abase = g_W + soff_tab[w - 1];
    int Kw  = w << 9;
    int nch = w << 3;                  // K / 64

    uint32_t sb = smem_to_u32(smem);
    int tid = threadIdx.x, wid = tid >> 5, lane = tid & 31;
    int wm = wid >> 2;                 // 0..1 : rows wm*64
    int wn = wid & 3;                  // 0..3 : cols wn*32

    const __half* XB = g_X + ((size_t)b * TP + t0) * H;

    auto load_stage = [&](int c, int s) {
        uint32_t st = sb + (uint32_t)s * 32768u;
        int dw = c >> 3, cc = c & 7;
        #pragma unroll
        for (int q = 0; q < 4; q++) {
            int idx  = q * 256 + tid;  // 0..1023
            int row  = idx >> 3;       // 0..127
            int col8 = idx & 7;
            uint32_t sw = SMEM_SWIZZLE_128B((uint32_t)(row * 128 + col8 * 16));
            CP_ASYNC_16(st + sw,          Abase + (size_t)row * Kw + c * 64 + col8 * 8);
            CP_ASYNC_16(st + 16384u + sw, XB + (size_t)(dw + row) * H + cc * 64 + col8 * 8);
        }
        CP_ASYNC_COMMIT();
    };

    float acc[4][4][4];
    #pragma unroll
    for (int mi = 0; mi < 4; mi++)
        #pragma unroll
        for (int ni = 0; ni < 4; ni++)
            #pragma unroll
            for (int e = 0; e < 4; e++) acc[mi][ni][e] = 0.0f;

    load_stage(0, 0);
    load_stage(1, 1);

    #pragma unroll 1
    for (int c = 0; c < nch; c++) {
        if (c + 2 < nch) { load_stage(c + 2, (c + 2) % 3); CP_ASYNC_WAIT(2); }
        else             { CP_ASYNC_WAIT(0); }
        __syncthreads();

        uint32_t st = sb + (uint32_t)(c % 3) * 32768u;
        #pragma unroll
        for (int ks = 0; ks < 4; ks++) {
            int k0 = ks * 16;
            uint32_t a[4][4];
            #pragma unroll
            for (int mi = 0; mi < 4; mi++) {
                int row = wm * 64 + mi * 16 + ((lane >> 3) & 1) * 8 + (lane & 7);
                int col = k0 + (lane >> 4) * 8;
                ldsm_x4(a[mi], st + SMEM_SWIZZLE_128B((uint32_t)(row * 128 + col * 2)));
            }
            uint32_t bh[2][4];
            #pragma unroll
            for (int nh = 0; nh < 2; nh++) {
                int row = wn * 32 + nh * 16 + (lane >> 4) * 8 + (lane & 7);
                int col = k0 + ((lane >> 3) & 1) * 8;
                ldsm_x4(bh[nh], st + 16384u + SMEM_SWIZZLE_128B((uint32_t)(row * 128 + col * 2)));
            }
            #pragma unroll
            for (int mi = 0; mi < 4; mi++)
                #pragma unroll
                for (int ni = 0; ni < 4; ni++)
                    mma_f16(acc[mi][ni], a[mi], &bh[ni >> 1][(ni & 1) * 2]);
        }
        __syncthreads();
    }

    // Epilogue: masked max over t, + bias, relu floor, atomicMax into g_feat.
    const float* bias = (w == 1) ? b1 : (w == 2) ? b2 : (w == 3) ? b3 : (w == 4) ? b4 : b5;
    float* featb = g_feat + (size_t)b * (5 * NF) + (size_t)(w - 1) * NF;

    #pragma unroll
    for (int mi = 0; mi < 4; mi++) {
        int f0 = wm * 64 + mi * 16 + (lane >> 2);
        float m0 = -1e30f, m1 = -1e30f;
        #pragma unroll
        for (int ni = 0; ni < 4; ni++) {
            int t = t0 + wn * 32 + ni * 8 + (lane & 3) * 2;
            if (t <= tmax)     { m0 = fmaxf(m0, acc[mi][ni][0]); m1 = fmaxf(m1, acc[mi][ni][2]); }
            if (t + 1 <= tmax) { m0 = fmaxf(m0, acc[mi][ni][1]); m1 = fmaxf(m1, acc[mi][ni][3]); }
        }
        #pragma unroll
        for (int o = 1; o <= 2; o <<= 1) {
            m0 = fmaxf(m0, __shfl_xor_sync(0xffffffffu, m0, o));
            m1 = fmaxf(m1, __shfl_xor_sync(0xffffffffu, m1, o));
        }
        if ((lane & 3) == 0) {
            float fa = fmaxf(0.0f, m0 + bias[f0]);
            float fb = fmaxf(0.0f, m1 + bias[f0 + 8]);
            atomicMax((int*)&featb[f0],     __float_as_int(fa));
            atomicMax((int*)&featb[f0 + 8], __float_as_int(fb));
        }
    }
}

// ---------------------------------------------------------------------------
// Collapsed FC: out[b] = sigmoid(feat_b . g_v + g_c). One warp per batch.
// ---------------------------------------------------------------------------
__global__ void __launch_bounds__(1024) fc_kernel(float* __restrict__ out) {
    int warp = threadIdx.x >> 5, lane = threadIdx.x & 31;
    int b = blockIdx.x * 32 + warp;
    if (b >= B) return;
    const float* feat = g_feat + (size_t)b * (5 * NF);
    float s = 0.0f;
    #pragma unroll
    for (int k = 0; k < 20; k++) {
        int j = k * 32 + lane;
        s += feat[j] * g_v[j];
    }
    #pragma unroll
    for (int off = 16; off > 0; off >>= 1)
        s += __shfl_xor_sync(0xffffffffu, s, off);
    if (lane == 0) out[b] = 1.0f / (1.0f + expf(-(s + g_c[0])));
}

// ---------------------------------------------------------------------------
extern "C" void kernel_launch(void* const* d_in, const int* in_sizes, int n_in,
                              void* d_out, int out_size) {
    const float* enc     = (const float*)d_in[0];
    const int*   lengths = (const int*)d_in[1];
    const float* w1 = (const float*)d_in[2];
    const float* cb1 = (const float*)d_in[3];
    const float* w2 = (const float*)d_in[4];
    const float* cb2 = (const float*)d_in[5];
    const float* w3 = (const float*)d_in[6];
    const float* cb3 = (const float*)d_in[7];
    const float* w4 = (const float*)d_in[8];
    const float* cb4 = (const float*)d_in[9];
    const float* w5 = (const float*)d_in[10];
    const float* cb5 = (const float*)d_in[11];
    const float* fc1_w = (const float*)d_in[12];
    const float* fc1_b = (const float*)d_in[13];
    const float* fc2_w = (const float*)d_in[14];
    const float* fc2_b = (const float*)d_in[15];
    float* out = (float*)d_out;

    static bool s_attr_done = false;
    if (!s_attr_done) {
        cudaFuncSetAttribute(gemm_kernel, cudaFuncAttributeMaxDynamicSharedMemorySize,
                             GEMM_SMEM_BYTES);
        s_attr_done = true;
    }

    prep_kernel<<<dim3(16, 16, 153), 256>>>(enc, lengths, w1, w2, w3, w4, w5,
                                            fc1_w, fc1_b, fc2_w, fc2_b);
    gemm_kernel<<<dim3(T / 128, B, 5), 256, GEMM_SMEM_BYTES>>>(lengths, cb1, cb2, cb3, cb4, cb5);
    fc_kernel<<<4, 1024>>>(out);
}